// round 5
// baseline (speedup 1.0000x reference)
#include <cuda_runtime.h>
#include <cstdint>

// Z gate (DIM=2, S=1) on wires {0,5,11} of a 24-qubit register.
//   out[n] = (-1)^popc(n & SIGN_MASK) * x_real[n]   (N float32)
// SIGN_MASK bits 23,18,12: constant across any 16-element aligned chunk,
// so one sign per thread handling 4 consecutive float4s.

#define NELEM    (1u << 24)
#define SIGN_MASK ((1u << 23) | (1u << 18) | (1u << 12))
#define V4_PER_THREAD 4u   // 4 float4 = 16 floats = 64 B per thread

__global__ void __launch_bounds__(256) z_phase_kernel(
    const float4* __restrict__ xr,
    float4* __restrict__ out)
{
    unsigned t = blockIdx.x * blockDim.x + threadIdx.x;
    unsigned v0 = t * V4_PER_THREAD;          // first float4 index
    unsigned n0 = v0 << 2;                    // first element index

    float s = (__popc(n0 & SIGN_MASK) & 1) ? -1.0f : 1.0f;

    // 4 independent loads, front-batched for MLP.
    float4 a = __ldcs(&xr[v0 + 0]);
    float4 b = __ldcs(&xr[v0 + 1]);
    float4 c = __ldcs(&xr[v0 + 2]);
    float4 d = __ldcs(&xr[v0 + 3]);

    a.x *= s; a.y *= s; a.z *= s; a.w *= s;
    b.x *= s; b.y *= s; b.z *= s; b.w *= s;
    c.x *= s; c.y *= s; c.z *= s; c.w *= s;
    d.x *= s; d.y *= s; d.z *= s; d.w *= s;

    __stcs(&out[v0 + 0], a);
    __stcs(&out[v0 + 1], b);
    __stcs(&out[v0 + 2], c);
    __stcs(&out[v0 + 3], d);
}

extern "C" void kernel_launch(void* const* d_in, const int* in_sizes, int n_in,
                              void* d_out, int out_size)
{
    const float4* xr = (const float4*)d_in[0];
    float4* out = (float4*)d_out;

    const unsigned threads = 256;
    const unsigned n_vec4 = NELEM / 4;                         // 4,194,304
    const unsigned nthreads = n_vec4 / V4_PER_THREAD;          // 1,048,576
    const unsigned blocks = nthreads / threads;                // 4096

    z_phase_kernel<<<blocks, threads>>>(xr, out);
}

// round 6
// speedup vs baseline: 1.3064x; 1.3064x over previous
#include <cuda_runtime.h>
#include <cstdint>

// Z gate (DIM=2, S=1) on wires {0,5,11} of a 24-qubit register.
//   out[n] = (-1)^popc(n & SIGN_MASK) * x_real[n]   (N float32)
// SIGN_MASK bits 23,18,12 -> sign constant over each 4096-element aligned block.
//
// Each CTA processes 1024 consecutive float4s (4096 elements): exactly one
// sign per CTA. Threads access base + k*256 + tid -> every warp load/store
// instruction is a contiguous, fully-coalesced 4KB access, with 4 independent
// loads in flight per thread (MLP=4).

#define SIGN_MASK ((1u << 23) | (1u << 18) | (1u << 12))
#define V4_PER_BLOCK 1024u            // float4s per CTA
#define THREADS 256u

__global__ void __launch_bounds__(256) z_phase_kernel(
    const float4* __restrict__ xr,
    float4* __restrict__ out)
{
    unsigned base = blockIdx.x * V4_PER_BLOCK;
    // Element index of CTA start = base*4; sign uniform across the CTA.
    float s = (__popc((base << 2) & SIGN_MASK) & 1) ? -1.0f : 1.0f;

    unsigned i0 = base + threadIdx.x;

    float4 a = __ldcs(&xr[i0 + 0u * THREADS]);
    float4 b = __ldcs(&xr[i0 + 1u * THREADS]);
    float4 c = __ldcs(&xr[i0 + 2u * THREADS]);
    float4 d = __ldcs(&xr[i0 + 3u * THREADS]);

    a.x *= s; a.y *= s; a.z *= s; a.w *= s;
    b.x *= s; b.y *= s; b.z *= s; b.w *= s;
    c.x *= s; c.y *= s; c.z *= s; c.w *= s;
    d.x *= s; d.y *= s; d.z *= s; d.w *= s;

    __stcs(&out[i0 + 0u * THREADS], a);
    __stcs(&out[i0 + 1u * THREADS], b);
    __stcs(&out[i0 + 2u * THREADS], c);
    __stcs(&out[i0 + 3u * THREADS], d);
}

extern "C" void kernel_launch(void* const* d_in, const int* in_sizes, int n_in,
                              void* d_out, int out_size)
{
    const float4* xr = (const float4*)d_in[0];
    float4* out = (float4*)d_out;

    const unsigned n_vec4 = (1u << 24) / 4u;           // 4,194,304 float4s
    const unsigned blocks = n_vec4 / V4_PER_BLOCK;     // 4096

    z_phase_kernel<<<blocks, THREADS>>>(xr, out);
}